// round 5
// baseline (speedup 1.0000x reference)
#include <cuda_runtime.h>
#include <cstdint>

// Problem constants
#define N_NODES 400
#define NM1     399                    // N_NODES - 1
#define E_EDGES (N_NODES * NM1)        // 159600
#define PAIRS   (E_EDGES / 2)          // 79800 float4 per batch image
#define BATCH   32
#define TOTAL_F4 (PAIRS * BATCH)       // 2,553,600 float4 total output

// The full output is the 1.28 MB edge-one-hot pattern tiled 32x CONTIGUOUSLY.
// So carve the 40.86 MB output into 1280 contiguous 31,920-byte windows that
// freely span batch boundaries. Each block builds its (wrapped) pattern window
// in SMEM and emits ONE cp.async.bulk store. Minimum possible op count.
#define NBLK     1280
#define WIN_F4   1995                  // float4 per block; 1995*16 = 31,920 B
#define THREADS  256

__device__ __forceinline__ float4 edge_pair_value(int pair,
                                                  const float* __restrict__ adj) {
    const int e0 = pair * 2;
    const int e1 = e0 + 1;
    // send = e / 399 ; k = e % 399 ; rec = k + (k >= send)
    const int s0 = e0 / NM1;
    const int k0 = e0 - s0 * NM1;
    const int r0 = k0 + (k0 >= s0 ? 1 : 0);
    const int s1 = e1 / NM1;
    const int k1 = e1 - s1 * NM1;
    const int r1 = k1 + (k1 >= s1 ? 1 : 0);
    const float a0 = __ldg(&adj[s0 * N_NODES + r0]);
    const float a1 = __ldg(&adj[s1 * N_NODES + r1]);
    const float t0 = (a0 != 0.0f) ? 1.0f : 0.0f;
    const float t1 = (a1 != 0.0f) ? 1.0f : 0.0f;
    return make_float4(1.0f - t0, t0, 1.0f - t1, t1);
}

__global__ __launch_bounds__(THREADS)
void nri_edge_onehot_bigbulk_kernel(const float* __restrict__ adj,
                                    float4* __restrict__ out) {
    __shared__ __align__(128) float4 buf[WIN_F4];

    const int start = blockIdx.x * WIN_F4;      // global float4 index (fits int)
    // Pattern index of the window start (one int mod per block).
    const int pair0 = start % PAIRS;

    #pragma unroll 4
    for (int i = threadIdx.x; i < WIN_F4; i += THREADS) {
        int pair = pair0 + i;
        if (pair >= PAIRS) pair -= PAIRS;       // window < PAIRS: wraps at most once
        buf[i] = edge_pair_value(pair, adj);
    }
    __syncthreads();

    // Order generic-proxy SMEM writes before async-proxy TMA read.
    asm volatile("fence.proxy.async.shared::cta;" ::: "memory");

    if (threadIdx.x == 0) {
        const uint32_t saddr = (uint32_t)__cvta_generic_to_shared(buf);
        const uint64_t dst = (uint64_t)((const char*)out + (size_t)start * 16);
        asm volatile(
            "cp.async.bulk.global.shared::cta.bulk_group [%0], [%1], %2;"
            :: "l"(dst), "r"(saddr), "n"(WIN_F4 * 16) : "memory");
        asm volatile("cp.async.bulk.commit_group;" ::: "memory");
        asm volatile("cp.async.bulk.wait_group 0;" ::: "memory");
    }
}

extern "C" void kernel_launch(void* const* d_in, const int* in_sizes, int n_in,
                              void* d_out, int out_size) {
    // Input order per reference setup_inputs():
    //   0: inputs  [32,400,12,1]   (unused)
    //   1: weather [32,12,4]       (unused)
    //   2: rel_rec [E,400]         (unused — indices recovered arithmetically)
    //   3: rel_send[E,400]         (unused)
    //   4: adj_matrix [400,400]    fp32
    const float* adj = (const float*)d_in[4];
    float4* out = (float4*)d_out;

    // NBLK * WIN_F4 == TOTAL_F4 exactly (1280 * 1995 == 2,553,600) — no tail.
    nri_edge_onehot_bigbulk_kernel<<<NBLK, THREADS>>>(adj, out);
}

// round 6
// speedup vs baseline: 1.0226x; 1.0226x over previous
#include <cuda_runtime.h>

// Problem constants
#define N_NODES 400
#define NM1     399                  // N_NODES - 1
#define E_EDGES (N_NODES * NM1)      // 159600
#define PAIRS   (E_EDGES / 2)        // 79800 float4 elements per batch image
#define BATCH   32
#define THREADS 256
#define NBLK    ((PAIRS + THREADS - 1) / THREADS)   // 312

// The [E,2] one-hot is identical across all 32 batch slots, and the chip-wide
// store path caps at ~4.3 TB/s regardless of mechanism (measured: STG, TMA,
// dual-path all equal). So: minimum-overhead design — each thread computes its
// pair value exactly ONCE and fires 32 independent STG.128s (one per batch
// slot). 79,800 threads; store issue cost ~1.6K cyc/SM << ~18K cyc drain time.
__global__ __launch_bounds__(THREADS)
void nri_edge_onehot_b32_kernel(const float* __restrict__ adj,
                                float4* __restrict__ out) {
    const int pair = blockIdx.x * THREADS + threadIdx.x;   // 0 .. PAIRS-1
    if (pair >= PAIRS) return;

    const int e0 = pair * 2;
    const int e1 = e0 + 1;

    // Recover (send, rec) from row-major off-diagonal enumeration:
    // send = e / 399 ; k = e % 399 ; rec = k + (k >= send)
    const int s0 = e0 / NM1;
    const int k0 = e0 - s0 * NM1;
    const int r0 = k0 + (k0 >= s0 ? 1 : 0);

    const int s1 = e1 / NM1;
    const int k1 = e1 - s1 * NM1;
    const int r1 = k1 + (k1 >= s1 ? 1 : 0);

    const float a0 = __ldg(&adj[s0 * N_NODES + r0]);
    const float a1 = __ldg(&adj[s1 * N_NODES + r1]);

    const float t0 = (a0 != 0.0f) ? 1.0f : 0.0f;
    const float t1 = (a1 != 0.0f) ? 1.0f : 0.0f;
    const float4 v = make_float4(1.0f - t0, t0, 1.0f - t1, t1);

    // Broadcast to all 32 batch slots: independent fire-and-forget STG.128s.
    float4* p = out + pair;
    #pragma unroll
    for (int b = 0; b < BATCH; b++) {
        p[(size_t)b * PAIRS] = v;
    }
}

extern "C" void kernel_launch(void* const* d_in, const int* in_sizes, int n_in,
                              void* d_out, int out_size) {
    // Input order per reference setup_inputs():
    //   0: inputs  [32,400,12,1]   (unused)
    //   1: weather [32,12,4]       (unused)
    //   2: rel_rec [E,400]         (unused — indices recovered arithmetically)
    //   3: rel_send[E,400]         (unused)
    //   4: adj_matrix [400,400]    fp32
    const float* adj = (const float*)d_in[4];
    float4* out = (float4*)d_out;

    nri_edge_onehot_b32_kernel<<<NBLK, THREADS>>>(adj, out);
}

// round 7
// speedup vs baseline: 1.2143x; 1.1875x over previous
#include <cuda_runtime.h>

// Problem constants
#define N_NODES 400
#define NM1     399                  // N_NODES - 1
#define E_EDGES (N_NODES * NM1)      // 159600
#define PAIRS   (E_EDGES / 2)        // 79800 float4 elements per batch image
#define BATCH   32
#define BPT     4                    // batches stored per thread (sweep: 1->9.95us, 8->9.41us, 32->10.56us)
#define BGROUPS (BATCH / BPT)        // grid.y = 8
#define THREADS 256
#define NBLKX   ((PAIRS + THREADS - 1) / THREADS)   // 312

// The [E,2] one-hot is identical across all 32 batch slots. Store throughput
// is pinned at a path-independent ~4.35 TB/s chip write-ingress ceiling
// (measured equal for STG, TMA bulk, and mixed). The only live knob is
// warp-level drain parallelism: BPT=4 doubles storing-warp count vs the
// best-so-far BPT=8 while keeping per-warp store chains short.
__global__ __launch_bounds__(THREADS)
void nri_edge_onehot_b4_kernel(const float* __restrict__ adj,
                               float4* __restrict__ out) {
    const int pair = blockIdx.x * THREADS + threadIdx.x;   // 0 .. PAIRS-1
    if (pair >= PAIRS) return;

    const int e0 = pair * 2;
    const int e1 = e0 + 1;

    // Recover (send, rec) from row-major off-diagonal enumeration:
    // send = e / 399 ; k = e % 399 ; rec = k + (k >= send)
    const int s0 = e0 / NM1;
    const int k0 = e0 - s0 * NM1;
    const int r0 = k0 + (k0 >= s0 ? 1 : 0);

    const int s1 = e1 / NM1;
    const int k1 = e1 - s1 * NM1;
    const int r1 = k1 + (k1 >= s1 ? 1 : 0);

    const float a0 = __ldg(&adj[s0 * N_NODES + r0]);
    const float a1 = __ldg(&adj[s1 * N_NODES + r1]);

    const float t0 = (a0 != 0.0f) ? 1.0f : 0.0f;
    const float t1 = (a1 != 0.0f) ? 1.0f : 0.0f;
    const float4 v = make_float4(1.0f - t0, t0, 1.0f - t1, t1);

    // Broadcast to BPT batch slots: independent fire-and-forget STG.128s.
    float4* p = out + (size_t)(blockIdx.y * BPT) * PAIRS + pair;
    #pragma unroll
    for (int b = 0; b < BPT; b++) {
        p[(size_t)b * PAIRS] = v;
    }
}

extern "C" void kernel_launch(void* const* d_in, const int* in_sizes, int n_in,
                              void* d_out, int out_size) {
    // Input order per reference setup_inputs():
    //   0: inputs  [32,400,12,1]   (unused)
    //   1: weather [32,12,4]       (unused)
    //   2: rel_rec [E,400]         (unused — indices recovered arithmetically)
    //   3: rel_send[E,400]         (unused)
    //   4: adj_matrix [400,400]    fp32
    const float* adj = (const float*)d_in[4];
    float4* out = (float4*)d_out;

    dim3 grid(NBLKX, BGROUPS);   // (312, 8)
    nri_edge_onehot_b4_kernel<<<grid, THREADS>>>(adj, out);
}